// round 11
// baseline (speedup 1.0000x reference)
#include <cuda_runtime.h>
#include <math.h>
#include <stdint.h>

// Problem constants
#define B_   4
#define N_   8400
#define NM_  32
#define H_   160
#define W_   160
#define D_   100
#define HW_  (H_*W_)          // 25600
#define OW_  640
#define OH_  640

// Fused kernel geometry: one block = (batch, band of 5 source rows)
#define BANDS    32
#define THRF     384          // 12 warps
#define MPX      1120         // 7 rows x 160 px mask tile

// smem layout (floats)
#define SC_OFF    0                       // coeffs [d][ch]        3200 floats
#define SM_OFF    (SC_OFF + D_ * NM_)     // mask double buf       2*1120
#define STG_OFF   (SM_OFF + 2 * MPX)      // stage 12 warps * 2 * 640
#define SMEM_FLTS (STG_OFF + 12 * 2 * OW_)
#define SMEM_BYTES (SMEM_FLTS * 4)        // 83,200 B

// Packed fp32x2 FMA (Blackwell FFMA2) — PTX-only
__device__ __forceinline__ float2 ffma2(float2 a, float2 b, float2 c) {
    union { float2 f; unsigned long long u; } ua, ub, uc, ur;
    ua.f = a; ub.f = b; uc.f = c;
    asm("fma.rn.f32x2 %0, %1, %2, %3;" : "=l"(ur.u) : "l"(ua.u), "l"(ub.u), "l"(uc.u));
    return ur.f;
}

// ---------------------------------------------------------------------------
// Fused: gather + GEMM + sigmoid + 4x bilinear + threshold + TMA row streams.
// grid (32 bands, 4 b); block 384. One wave of 128 blocks.
// Thread t owns mask pixels p = t, t+384, t+768 of the 7x160 band tile and
// holds their 32-channel proto values in registers (pairs for FFMA2).
// Per d: mask -> barrier -> interp rows (warp w: jr = w, w+12) -> TMA.
// ---------------------------------------------------------------------------
__global__ void __launch_bounds__(THRF, 1)
fusedK(const float* __restrict__ mc,
       const float* __restrict__ proto,
       const void*  __restrict__ det,
       float* __restrict__ out)
{
    extern __shared__ float smem[];
    float* sc    = smem + SC_OFF;     // [d][ch]
    float* smA   = smem + SM_OFF;     // mask buffers (2 x 1120)
    float* stage = smem + STG_OFF;

    const int band = blockIdx.x;          // 0..31
    const int b    = blockIdx.y;
    const int R0   = 5 * band - 1;        // first source row of slab (pre-clamp)
    const int t    = threadIdx.x;
    const int w    = t >> 5;
    const int lane = t & 31;

    // --- det dtype detection (int64 values < 2^31 -> odd words all zero) ---
    const int* d32 = (const int*)det;
    bool is64 = true;
    #pragma unroll
    for (int k = 0; k < 8; k++) if (d32[2 * k + 1] != 0) is64 = false;

    // --- coeff gather: sc[d][ch], float4 over ch ---
    for (int i = t; i < D_ * 8; i += THRF) {
        const int d = i >> 3;
        const int q = i & 7;
        long long idx = is64 ? ((const long long*)det)[b * D_ + d]
                             : (long long)d32[b * D_ + d];
        idx = min(max(idx, 0LL), (long long)(N_ - 1));
        const float4 v = *reinterpret_cast<const float4*>(
            mc + ((long long)b * N_ + idx) * NM_ + 4 * q);
        *reinterpret_cast<float4*>(&sc[d * NM_ + 4 * q]) = v;
    }

    // --- proto slab into registers: 3 px x 16 channel-pairs ---
    float2 pr[3][NM_ / 2];
    #pragma unroll
    for (int s = 0; s < 3; s++) {
        const int p  = t + THRF * s;
        const int pc = min(p, MPX - 1);
        const int row = pc / 160;
        const int x   = pc % 160;
        const int gr  = min(max(R0 + row, 0), H_ - 1);
        const float* src = proto + (size_t)b * NM_ * HW_ + (size_t)gr * W_ + x;
        #pragma unroll
        for (int k = 0; k < NM_ / 2; k++) {
            pr[s][k].x = src[(size_t)(2 * k)     * HW_];
            pr[s][k].y = src[(size_t)(2 * k + 1) * HW_];
        }
    }
    __syncthreads();

    const char* gb = (const char*)(out + (size_t)b * D_ * (OH_ * OW_));
    unsigned cnt = 0;                     // per-warp TMA row counter

    for (int d = 0; d < D_; d++) {
        float* smb = smA + (d & 1) * MPX;

        // ---- mask phase: 48 FFMA2 + sigmoid per thread ----
        {
            const float4* cq = reinterpret_cast<const float4*>(&sc[d * NM_]);
            float2 a0 = make_float2(0.f, 0.f);
            float2 a1 = make_float2(0.f, 0.f);
            float2 a2 = make_float2(0.f, 0.f);
            #pragma unroll
            for (int q = 0; q < 8; q++) {
                const float4 c = cq[q];
                const float2 ce = make_float2(c.x, c.y);
                const float2 co = make_float2(c.z, c.w);
                a0 = ffma2(ce, pr[0][2 * q], a0);
                a0 = ffma2(co, pr[0][2 * q + 1], a0);
                a1 = ffma2(ce, pr[1][2 * q], a1);
                a1 = ffma2(co, pr[1][2 * q + 1], a1);
                a2 = ffma2(ce, pr[2][2 * q], a2);
                a2 = ffma2(co, pr[2][2 * q + 1], a2);
            }
            const float m0 = 1.f / (1.f + expf(-(a0.x + a0.y)));
            const float m1 = 1.f / (1.f + expf(-(a1.x + a1.y)));
            const float m2 = 1.f / (1.f + expf(-(a2.x + a2.y)));
            smb[t]              = m0;
            smb[t + THRF]       = m1;
            if (t + 2 * THRF < MPX) smb[t + 2 * THRF] = m2;
        }
        __syncthreads();   // mask(d) ready; also guarantees interp(d-1) done

        // ---- interp phase: warp w does output rows jr = w, w+12 ----
        const char* gout = gb + (size_t)d * (OH_ * OW_ * 4);
        for (int jr = w; jr < 20; jr += 12) {
            const int y  = 20 * band + jr;
            const int yy = y - 2;
            const int g  = (yy >= 0) ? (yy >> 2) : -1;
            const int k  = yy - 4 * g;
            const float fy = 0.125f + 0.25f * (float)k;

            const float* row0 = smb + (g - R0) * 160;
            const float* row1 = smb + (g + 1 - R0) * 160;

            float* srow = stage + (w * 2 + (cnt & 1)) * OW_;
            if (cnt >= 2) {
                if (lane == 0)
                    asm volatile("cp.async.bulk.wait_group.read 1;" ::: "memory");
            }
            __syncwarp();

            #pragma unroll
            for (int j = 0; j < 5; j++) {
                const int c  = 32 * j + lane;
                const int cm = max(c - 1, 0);
                const int cp = min(c + 1, W_ - 1);

                const float a0 = row0[cm], a1 = row0[c], a2 = row0[cp];
                const float b0 = row1[cm], b1 = row1[c], b2 = row1[cp];
                const float v0 = fmaf(fy, b0 - a0, a0);
                const float v1 = fmaf(fy, b1 - a1, a1);
                const float v2 = fmaf(fy, b2 - a2, a2);
                const float da = v1 - v0;
                const float db = v2 - v1;

                float4 o;
                o.x = (fmaf(0.625f, da, v0) > 0.5f) ? 1.0f : 0.0f;
                o.y = (fmaf(0.875f, da, v0) > 0.5f) ? 1.0f : 0.0f;
                o.z = (fmaf(0.125f, db, v1) > 0.5f) ? 1.0f : 0.0f;
                o.w = (fmaf(0.375f, db, v1) > 0.5f) ? 1.0f : 0.0f;
                *reinterpret_cast<float4*>(srow + 4 * c) = o;
            }

            asm volatile("fence.proxy.async.shared::cta;" ::: "memory");
            __syncwarp();
            if (lane == 0) {
                const uint32_t s32 = (uint32_t)__cvta_generic_to_shared(srow);
                asm volatile("cp.async.bulk.global.shared::cta.bulk_group [%0], [%1], %2;"
                             :: "l"(gout + (size_t)y * (OW_ * 4)),
                                "r"(s32), "r"((uint32_t)(OW_ * 4))
                             : "memory");
                asm volatile("cp.async.bulk.commit_group;" ::: "memory");
            }
            cnt++;
        }
        // no trailing barrier: next mask writes the other buffer; the next
        // mask-barrier orders reuse of this one.
    }

    if (lane == 0)
        asm volatile("cp.async.bulk.wait_group 0;" ::: "memory");
}

// ---------------------------------------------------------------------------
extern "C" void kernel_launch(void* const* d_in, const int* in_sizes, int n_in,
                              void* d_out, int out_size)
{
    // Size-based binding (robust to order/units): det << mc < proto
    const float* mc    = nullptr;
    const float* proto = nullptr;
    const void*  det   = nullptr;

    for (int i = 0; i < n_in; i++) {
        const long long s = in_sizes[i];
        if      (s == 1075200LL || s == 4300800LL)                        mc    = (const float*)d_in[i];
        else if (s == 3276800LL || s == 13107200LL)                       proto = (const float*)d_in[i];
        else if (s == 400LL || s == 800LL || s == 1600LL || s == 3200LL)  det   = d_in[i];
    }
    if (!mc || !proto || !det) {
        int imin = 0, imax = 0;
        for (int i = 1; i < 3 && i < n_in; i++) {
            if (in_sizes[i] < in_sizes[imin]) imin = i;
            if (in_sizes[i] > in_sizes[imax]) imax = i;
        }
        const int imid = 3 - imin - imax;
        det   = d_in[imin];
        proto = (const float*)d_in[imax];
        mc    = (const float*)d_in[imid];
    }

    float* out = (float*)d_out;     // [4,100,640,640] f32 (0.0/1.0)
    (void)out_size;

    cudaFuncSetAttribute(fusedK, cudaFuncAttributeMaxDynamicSharedMemorySize, SMEM_BYTES);
    fusedK<<<dim3(BANDS, B_), THRF, SMEM_BYTES>>>(mc, proto, det, out);
}

// round 12
// speedup vs baseline: 1.0888x; 1.0888x over previous
#include <cuda_runtime.h>
#include <math.h>
#include <stdint.h>

// Problem constants
#define B_   4
#define N_   8400
#define NM_  32
#define H_   160
#define W_   160
#define D_   100
#define HW_  (H_*W_)          // 25600
#define OW_  640
#define OH_  640

// Scratch: sigmoid masks [B][D][H][W] fp32 = 40.96 MB
__device__ float g_S[(size_t)B_ * D_ * HW_];

// Packed fp32x2 FMA (Blackwell FFMA2) — PTX-only
__device__ __forceinline__ float2 ffma2(float2 a, float2 b, float2 c) {
    union { float2 f; unsigned long long u; } ua, ub, uc, ur;
    ua.f = a; ub.f = b; uc.f = c;
    asm("fma.rn.f32x2 %0, %1, %2, %3;" : "=l"(ur.u) : "l"(ua.u), "l"(ub.u), "l"(uc.u));
    return ur.f;
}

// ---------------------------------------------------------------------------
// Kernel A (R8 design): coeff gather + GEMM over NM=32 + sigmoid -> g_S.
// Launched per d-half: grid (25, 5, 4); block 256; 3 CTAs/SM.
// Thread: 4 adjacent px x 10 d via FFMA2.
// ---------------------------------------------------------------------------
#define DT_  10
#define PXT_ 4

__global__ void __launch_bounds__(256, 3)
kernelA(const float* __restrict__ mc,
        const float* __restrict__ proto,
        const void* __restrict__ det,      // int32 vs int64 detected on device
        const int dBase)
{
    const int b  = blockIdx.z;
    const int d0 = dBase + blockIdx.y * DT_;
    const int p0 = blockIdx.x * (256 * PXT_) + threadIdx.x * PXT_;

    // int64 det values < 2^31 -> all odd int32 words zero
    const int* d32 = (const int*)det;
    bool is64 = true;
    #pragma unroll
    for (int k = 0; k < 8; k++) if (d32[2 * k + 1] != 0) is64 = false;

    __shared__ float sc[NM_][DT_];
    for (int i = threadIdx.x; i < NM_ * DT_; i += 256) {
        const int n = i / DT_;
        const int d = i % DT_;
        const int flat = b * D_ + d0 + d;
        long long idx = is64 ? ((const long long*)det)[flat] : (long long)d32[flat];
        idx = min(max(idx, 0LL), (long long)(N_ - 1));
        sc[n][d] = mc[((long long)b * N_ + idx) * NM_ + n];
    }
    __syncthreads();

    float2 acc[DT_][2];
    #pragma unroll
    for (int d = 0; d < DT_; d++) {
        acc[d][0] = make_float2(0.f, 0.f);
        acc[d][1] = make_float2(0.f, 0.f);
    }

    const float* pbase = proto + (size_t)b * NM_ * HW_ + p0;

    #pragma unroll 8
    for (int n = 0; n < NM_; n++) {
        const float4 p = *reinterpret_cast<const float4*>(pbase + (size_t)n * HW_);
        const float2 pa = make_float2(p.x, p.y);
        const float2 pb = make_float2(p.z, p.w);
        #pragma unroll
        for (int d = 0; d < DT_; d++) {
            const float c = sc[n][d];
            const float2 cc = make_float2(c, c);
            acc[d][0] = ffma2(pa, cc, acc[d][0]);
            acc[d][1] = ffma2(pb, cc, acc[d][1]);
        }
    }

    #pragma unroll
    for (int d = 0; d < DT_; d++) {
        float4 s;
        s.x = 1.0f / (1.0f + expf(-acc[d][0].x));
        s.y = 1.0f / (1.0f + expf(-acc[d][0].y));
        s.z = 1.0f / (1.0f + expf(-acc[d][1].x));
        s.w = 1.0f / (1.0f + expf(-acc[d][1].y));
        *reinterpret_cast<float4*>(g_S + ((size_t)(b * D_ + d0 + d)) * HW_ + p0) = s;
    }
}

// ---------------------------------------------------------------------------
// Kernel B (R9 design): 4x bilinear upsample + threshold; per-warp row
// pipelines with per-row TMA bulk stores (double-buffered, wait_group.read 1).
// Launched per d-half: grid (8 bands, 50 d, 4 b); block 256 (8 warps);
// smem 55.0 KB -> 4 CTAs/SM. Warp w: rows Y0 + w + 8*ri, ri 0..9.
// ---------------------------------------------------------------------------
#define SRCROWS      22                                  // 20 + 2 halo
#define BAND_FLOATS  (SRCROWS * 160)                     // 3520 floats
#define ROW_FLOATS   OW_                                 // 640 floats = 2560 B
#define SMEMB_BYTES  ((BAND_FLOATS + 8 * 2 * ROW_FLOATS) * 4)   // 55040 B

__global__ void __launch_bounds__(256)
kernelB(float* __restrict__ out, const int dBase)
{
    extern __shared__ float smem[];
    float* sS = smem;                                    // [22][160] band

    const int band = blockIdx.x;                         // 0..7
    const int d    = dBase + blockIdx.y;
    const int b    = blockIdx.z;
    const int R0   = 20 * band - 1;                      // first band source row
    const int Y0   = 80 * band;

    // load source band (smem row r holds global row clamp(R0 + r))
    const float* Sg = g_S + ((size_t)(b * D_ + d)) * HW_;
    for (int i = threadIdx.x; i < SRCROWS * 40; i += 256) {
        const int r  = i / 40;
        const int x4 = i % 40;
        const int gr = min(max(R0 + r, 0), H_ - 1);
        *reinterpret_cast<float4*>(&sS[r * 160 + x4 * 4]) =
            *reinterpret_cast<const float4*>(Sg + gr * 160 + x4 * 4);
    }
    __syncthreads();

    const int w    = threadIdx.x >> 5;
    const int lane = threadIdx.x & 31;
    float* wstage = smem + BAND_FLOATS + w * (2 * ROW_FLOATS);
    const char* gbase = (const char*)(out + ((size_t)(b * D_ + d)) * (OH_ * OW_));

    for (int ri = 0; ri < 10; ri++) {
        const int y   = Y0 + w + 8 * ri;
        const int buf = ri & 1;
        float* srow = wstage + buf * ROW_FLOATS;

        // before overwriting this buffer, ensure TMA finished READING it
        if (ri >= 2) {
            if (lane == 0)
                asm volatile("cp.async.bulk.wait_group.read 1;" ::: "memory");
        }
        __syncwarp();

        const int yy = y - 2;
        const int g  = (yy >= 0) ? (yy >> 2) : -1;
        const int k  = yy - 4 * g;
        const float fy = 0.125f + 0.25f * (float)k;

        const float* row0 = &sS[(min(max(g, 0), H_ - 1) - R0) * 160];
        const float* row1 = &sS[(min(g + 1,     H_ - 1) - R0) * 160];

        #pragma unroll
        for (int j = 0; j < 5; j++) {
            const int c  = 32 * j + lane;
            const int cm = max(c - 1, 0);
            const int cp = min(c + 1, W_ - 1);

            const float a0 = row0[cm], a1 = row0[c], a2 = row0[cp];
            const float b0 = row1[cm], b1 = row1[c], b2 = row1[cp];
            const float v0 = fmaf(fy, b0 - a0, a0);
            const float v1 = fmaf(fy, b1 - a1, a1);
            const float v2 = fmaf(fy, b2 - a2, a2);
            const float da = v1 - v0;
            const float db = v2 - v1;

            float4 o;
            o.x = (fmaf(0.625f, da, v0) > 0.5f) ? 1.0f : 0.0f;
            o.y = (fmaf(0.875f, da, v0) > 0.5f) ? 1.0f : 0.0f;
            o.z = (fmaf(0.125f, db, v1) > 0.5f) ? 1.0f : 0.0f;
            o.w = (fmaf(0.375f, db, v1) > 0.5f) ? 1.0f : 0.0f;
            *reinterpret_cast<float4*>(srow + 4 * c) = o;
        }

        // make STS visible to the async proxy, then one lane issues the copy
        asm volatile("fence.proxy.async.shared::cta;" ::: "memory");
        __syncwarp();
        if (lane == 0) {
            const uint32_t s32 = (uint32_t)__cvta_generic_to_shared(srow);
            asm volatile("cp.async.bulk.global.shared::cta.bulk_group [%0], [%1], %2;"
                         :: "l"(gbase + (size_t)y * (OW_ * 4)),
                            "r"(s32), "r"((uint32_t)(ROW_FLOATS * 4))
                         : "memory");
            asm volatile("cp.async.bulk.commit_group;" ::: "memory");
        }
    }

    // full completion before kernel end
    if (lane == 0)
        asm volatile("cp.async.bulk.wait_group 0;" ::: "memory");
}

// ---------------------------------------------------------------------------
extern "C" void kernel_launch(void* const* d_in, const int* in_sizes, int n_in,
                              void* d_out, int out_size)
{
    // Size-based binding (robust to order/units): det << mc < proto
    const float* mc    = nullptr;
    const float* proto = nullptr;
    const void*  det   = nullptr;

    for (int i = 0; i < n_in; i++) {
        const long long s = in_sizes[i];
        if      (s == 1075200LL || s == 4300800LL)                        mc    = (const float*)d_in[i];
        else if (s == 3276800LL || s == 13107200LL)                       proto = (const float*)d_in[i];
        else if (s == 400LL || s == 800LL || s == 1600LL || s == 3200LL)  det   = d_in[i];
    }
    if (!mc || !proto || !det) {
        int imin = 0, imax = 0;
        for (int i = 1; i < 3 && i < n_in; i++) {
            if (in_sizes[i] < in_sizes[imin]) imin = i;
            if (in_sizes[i] > in_sizes[imax]) imax = i;
        }
        const int imid = 3 - imin - imax;
        det   = d_in[imin];
        proto = (const float*)d_in[imax];
        mc    = (const float*)d_in[imid];
    }

    float* out = (float*)d_out;     // [4,100,640,640] f32 (0.0/1.0)
    (void)out_size;

    cudaFuncSetAttribute(kernelB, cudaFuncAttributeMaxDynamicSharedMemorySize, SMEMB_BYTES);

    // Two-phase d-split pipeline: A1 -> {B1 || A2} -> B2.
    // Each A-half is grid 500 (one full wave at 3 CTAs/SM) so A stays
    // efficient; B-halves are grid 1600. Fork/join via events
    // (graph-capture-native). Objects created fresh each call; intentionally
    // not destroyed (destroy mid-capture is illegal; harness calls this only
    // a few times).
    cudaStream_t s;
    cudaStreamCreateWithFlags(&s, cudaStreamNonBlocking);
    cudaEvent_t evA1, evA2, evB;
    cudaEventCreateWithFlags(&evA1, cudaEventDisableTiming);
    cudaEventCreateWithFlags(&evA2, cudaEventDisableTiming);
    cudaEventCreateWithFlags(&evB,  cudaEventDisableTiming);

    kernelA<<<dim3(HW_ / (256 * PXT_), 5, B_), 256>>>(mc, proto, det, 0);
    cudaEventRecord(evA1, 0);
    kernelA<<<dim3(HW_ / (256 * PXT_), 5, B_), 256>>>(mc, proto, det, 50);
    cudaEventRecord(evA2, 0);

    cudaStreamWaitEvent(s, evA1, 0);
    kernelB<<<dim3(8, 50, B_), 256, SMEMB_BYTES, s>>>(out, 0);
    cudaStreamWaitEvent(s, evA2, 0);
    kernelB<<<dim3(8, 50, B_), 256, SMEMB_BYTES, s>>>(out, 50);

    cudaEventRecord(evB, s);
    cudaStreamWaitEvent(0, evB, 0);
}